// round 1
// baseline (speedup 1.0000x reference)
#include <cuda_runtime.h>
#include <math.h>

#define TFULL 2048
#define DM    1024
#define LDQKV 1536   // [Q(1024) | K(256) | V(256)]

// Scratch (static device globals — no allocation allowed)
__device__ float g_qkv[2 * TFULL * LDQKV];  // 25.2 MB
__device__ float g_att[2 * TFULL * DM];     // 16.8 MB

// ---------------------------------------------------------------------------
// C[M,N] = A[M,K] @ B[N,K]^T   (A,B row-major, C row-major with ldc)
// 64x64 tile, BK=16, 256 threads, 4x4 microtile per thread.
// M=4096 fixed via grid.y=64; N via grid.x*64; K multiple of 16.
// ---------------------------------------------------------------------------
__global__ __launch_bounds__(256)
void sgemm_abt(const float* __restrict__ A, const float* __restrict__ B,
               float* __restrict__ C, int K, int ldc) {
    __shared__ float As[16][68];
    __shared__ float Bs[16][68];
    const int tid = threadIdx.x;
    const int m0 = blockIdx.y * 64;
    const int n0 = blockIdx.x * 64;
    const int tx = tid & 15, ty = tid >> 4;
    const int r  = tid >> 2;            // 0..63 (row within tile to load)
    const int c4 = (tid & 3) * 4;       // 0,4,8,12 (k offset to load)

    float acc[4][4];
#pragma unroll
    for (int i = 0; i < 4; i++)
#pragma unroll
        for (int j = 0; j < 4; j++) acc[i][j] = 0.f;

    const float* Ap = A + (size_t)(m0 + r) * K + c4;
    const float* Bp = B + (size_t)(n0 + r) * K + c4;

    for (int kc = 0; kc < K; kc += 16) {
        float4 av = *(const float4*)(Ap + kc);
        float4 bv = *(const float4*)(Bp + kc);
        As[c4 + 0][r] = av.x; As[c4 + 1][r] = av.y;
        As[c4 + 2][r] = av.z; As[c4 + 3][r] = av.w;
        Bs[c4 + 0][r] = bv.x; Bs[c4 + 1][r] = bv.y;
        Bs[c4 + 2][r] = bv.z; Bs[c4 + 3][r] = bv.w;
        __syncthreads();
#pragma unroll
        for (int kk = 0; kk < 16; kk++) {
            float4 a4 = *(const float4*)&As[kk][ty * 4];
            float4 b4 = *(const float4*)&Bs[kk][tx * 4];
            float aa[4] = {a4.x, a4.y, a4.z, a4.w};
            float bb[4] = {b4.x, b4.y, b4.z, b4.w};
#pragma unroll
            for (int i = 0; i < 4; i++)
#pragma unroll
                for (int j = 0; j < 4; j++) acc[i][j] += aa[i] * bb[j];
        }
        __syncthreads();
    }

    float* Cp = C + (size_t)(m0 + ty * 4) * ldc + n0 + tx * 4;
#pragma unroll
    for (int i = 0; i < 4; i++) {
        float4 out = make_float4(acc[i][0], acc[i][1], acc[i][2], acc[i][3]);
        *(float4*)(Cp + (size_t)i * ldc) = out;
    }
}

// ---------------------------------------------------------------------------
// In-place interleaved RoPE over Q (cols 0..1023) and K (cols 1024..1279).
// Pair p: c0 = 2p. Both segments are 64-aligned so pp = (c0 & 63) >> 1.
// ---------------------------------------------------------------------------
__global__ void rope_kernel(float* __restrict__ QKV, const int* __restrict__ tpos) {
    const int row = blockIdx.x;                 // 0..4095 (b*t)
    const int t = row & (TFULL - 1);
    const float pos = (float)tpos[t];
    float* rp = QKV + (size_t)row * LDQKV;
    for (int p = threadIdx.x; p < 640; p += blockDim.x) {
        const int c0 = 2 * p;
        const int pp = (c0 & 63) >> 1;
        // theta^(-pp/32) = exp(-ln(10000)/32 * pp)
        const float inv_freq = __expf(-0.28782313662425572f * (float)pp);
        const float ang = pos * inv_freq;
        float s, c;
        sincosf(ang, &s, &c);
        const float x1 = rp[c0], x2 = rp[c0 + 1];
        rp[c0]     = x1 * c - x2 * s;
        rp[c0 + 1] = x1 * s + x2 * c;
    }
}

// ---------------------------------------------------------------------------
// Sliding-window causal attention, online softmax.
// Grid: (t/128, heads=16, b=2), block 128 threads, 1 thread = 1 query.
// K/V for the block's key span staged through SMEM in 32-key chunks.
// ---------------------------------------------------------------------------
__global__ __launch_bounds__(128)
void attn_kernel(const float* __restrict__ QKV, float* __restrict__ O) {
    __shared__ float4 Ks[32][16];
    __shared__ float4 Vs[32][16];
    const int tid = threadIdx.x;
    const int i0 = blockIdx.x * 128;
    const int h  = blockIdx.y;
    const int bb = blockIdx.z;
    const int g  = h >> 2;
    const int i  = i0 + tid;

    // Load query row, pre-scaled by 1/sqrt(64)
    const float* qrow = QKV + ((size_t)(bb * TFULL + i)) * LDQKV + h * 64;
    float4 q4[16];
#pragma unroll
    for (int u = 0; u < 16; u++) {
        float4 v = *(const float4*)(qrow + 4 * u);
        v.x *= 0.125f; v.y *= 0.125f; v.z *= 0.125f; v.w *= 0.125f;
        q4[u] = v;
    }

    float m = -1e30f, l = 0.f;
    float4 acc[16];
#pragma unroll
    for (int u = 0; u < 16; u++) acc[u] = make_float4(0.f, 0.f, 0.f, 0.f);

    const int j0   = (i0 - 512 > 0) ? (i0 - 512) : 0;   // multiple of 32
    const int jend = i0 + 127;

    for (int jc = j0; jc <= jend; jc += 32) {
        __syncthreads();
        // cooperative load of 32 K rows + 32 V rows (always in [0,2048))
        for (int idx = tid; idx < 512; idx += 128) {
            const int rr = idx >> 4, cc = idx & 15;
            const size_t base = ((size_t)(bb * TFULL + jc + rr)) * LDQKV + g * 64 + 4 * cc;
            Ks[rr][cc] = *(const float4*)(QKV + base + 1024);
            Vs[rr][cc] = *(const float4*)(QKV + base + 1280);
        }
        __syncthreads();

        int rlo = (i - 512) - jc; if (rlo < 0) rlo = 0;
        int rmax = i - jc;        if (rmax > 31) rmax = 31;

        for (int rr = rlo; rr <= rmax; rr++) {
            float s = 0.f;
#pragma unroll
            for (int u = 0; u < 16; u++) {
                float4 k4 = Ks[rr][u];
                s += q4[u].x * k4.x + q4[u].y * k4.y + q4[u].z * k4.z + q4[u].w * k4.w;
            }
            if (s > m) {
                const float corr = __expf(m - s);
                l *= corr;
#pragma unroll
                for (int u = 0; u < 16; u++) {
                    acc[u].x *= corr; acc[u].y *= corr;
                    acc[u].z *= corr; acc[u].w *= corr;
                }
                m = s;
            }
            const float p = __expf(s - m);
            l += p;
#pragma unroll
            for (int u = 0; u < 16; u++) {
                float4 v4 = Vs[rr][u];
                acc[u].x += p * v4.x; acc[u].y += p * v4.y;
                acc[u].z += p * v4.z; acc[u].w += p * v4.w;
            }
        }
    }

    const float inv = 1.f / l;
    float* orow = O + ((size_t)(bb * TFULL + i)) * DM + h * 64;
#pragma unroll
    for (int u = 0; u < 16; u++) {
        float4 v = acc[u];
        v.x *= inv; v.y *= inv; v.z *= inv; v.w *= inv;
        *(float4*)(orow + 4 * u) = v;
    }
}

// ---------------------------------------------------------------------------
extern "C" void kernel_launch(void* const* d_in, const int* in_sizes, int n_in,
                              void* d_out, int out_size) {
    const float* x  = (const float*)d_in[0];
    const float* WQ = (const float*)d_in[1];
    const float* WK = (const float*)d_in[2];
    const float* WV = (const float*)d_in[3];
    const float* WO = (const float*)d_in[4];
    const int* tpos = (const int*)d_in[5];

    float *qkv, *att;
    cudaGetSymbolAddress((void**)&qkv, g_qkv);
    cudaGetSymbolAddress((void**)&att, g_att);

    // QKV projections (fused output buffer, ldc = 1536)
    sgemm_abt<<<dim3(16, 64), 256>>>(x, WQ, qkv + 0,    1024, LDQKV);
    sgemm_abt<<<dim3(4,  64), 256>>>(x, WK, qkv + 1024, 1024, LDQKV);
    sgemm_abt<<<dim3(4,  64), 256>>>(x, WV, qkv + 1280, 1024, LDQKV);

    // RoPE on Q and K in place
    rope_kernel<<<2 * TFULL, 128>>>(qkv, tpos);

    // Sliding-window attention
    attn_kernel<<<dim3(TFULL / 128, 16, 2), 128>>>(qkv, att);

    // Output projection straight into d_out
    sgemm_abt<<<dim3(16, 64), 256>>>(att, WO, (float*)d_out, 1024, 1024);
}

// round 3
// speedup vs baseline: 1.6633x; 1.6633x over previous
#include <cuda_runtime.h>
#include <cuda_bf16.h>
#include <math.h>
#include <stdint.h>

#define TFULL 2048
#define DM    1024
#define LDQKV 1536   // [Q(1024) | K(256) | V(256)]

// Scratch (static device globals — no allocation allowed)
__device__ float g_qkv[2 * TFULL * LDQKV];   // 25.2 MB
__device__ float g_att[2 * TFULL * DM];      // 16.8 MB
__device__ float g_wcat[1536 * 1024];        // 6.3 MB (concat WQ|WK|WV)

// ===========================================================================
// Helpers
// ===========================================================================
__device__ __forceinline__ uint32_t smem_u32(const void* p) {
    uint32_t a;
    asm("{ .reg .u64 t; cvta.to.shared.u64 t, %1; cvt.u32.u64 %0, t; }"
        : "=r"(a) : "l"(p));
    return a;
}
__device__ __forceinline__ void ldsm_x4(uint32_t& r0, uint32_t& r1, uint32_t& r2,
                                        uint32_t& r3, uint32_t addr) {
    asm volatile("ldmatrix.sync.aligned.m8n8.x4.shared.b16 {%0,%1,%2,%3}, [%4];"
                 : "=r"(r0), "=r"(r1), "=r"(r2), "=r"(r3) : "r"(addr));
}
__device__ __forceinline__ void mma_bf16(float* c, const uint32_t* a, const uint32_t* b) {
    asm volatile(
        "mma.sync.aligned.m16n8k16.row.col.f32.bf16.bf16.f32 "
        "{%0,%1,%2,%3}, {%4,%5,%6,%7}, {%8,%9}, {%0,%1,%2,%3};"
        : "+f"(c[0]), "+f"(c[1]), "+f"(c[2]), "+f"(c[3])
        : "r"(a[0]), "r"(a[1]), "r"(a[2]), "r"(a[3]), "r"(b[0]), "r"(b[1]));
}
// pack two floats to bf16x2 (a -> lower, b -> upper), round-to-nearest
__device__ __forceinline__ uint32_t pack_bf16(float a, float b) {
    uint32_t r;
    asm("cvt.rn.bf16x2.f32 %0, %1, %2;" : "=r"(r) : "f"(b), "f"(a));
    return r;
}
// split pair: hi = bf16(x), lo = bf16(x - hi)
__device__ __forceinline__ void split2(float x0, float x1, uint32_t& hi, uint32_t& lo) {
    hi = pack_bf16(x0, x1);
    float h0 = __bfloat162float(__ushort_as_bfloat16((unsigned short)(hi & 0xFFFF)));
    float h1 = __bfloat162float(__ushort_as_bfloat16((unsigned short)(hi >> 16)));
    lo = pack_bf16(x0 - h0, x1 - h1);
}
#define SW128(off) ((off) ^ (((off) >> 3) & 0x70))

// ===========================================================================
// 3xBF16 split GEMM via mma.sync: C[4096, N] = A[4096,1024] @ B[N,1024]^T
// CTA tile 128x128, 8 warps (4 M x 2 N), warp tile 32x64. K-chunk 32.
// SMEM row layout (128B): [hi: 32 bf16 (64B) | lo: 32 bf16 (64B)], SW128.
// Buffers: [buf][A(16KB) | B(16KB)], double buffered = 64KB.
// ===========================================================================
#define GK 1024
#define SM_GEMM 65536

__global__ __launch_bounds__(256, 1)
void gemm_bf16x3(const float* __restrict__ A, const float* __restrict__ B,
                 float* __restrict__ C, int ldc) {
    extern __shared__ char sm[];
    const uint32_t smb = smem_u32(sm);
    const int tid = threadIdx.x;
    const int lid = tid & 31;
    const int wid = tid >> 5;
    const int wm = wid & 3;
    const int wn = wid >> 2;
    const int m0 = blockIdx.y * 128;
    const int n0 = blockIdx.x * 128;

    float acc[2][8][4];
#pragma unroll
    for (int s = 0; s < 2; s++)
#pragma unroll
        for (int j = 0; j < 8; j++)
#pragma unroll
            for (int q = 0; q < 4; q++) acc[s][j][q] = 0.f;

    // Staged global loads (32 floats A + 32 floats B per thread per chunk)
    float4 sA[2][2], sB[2][2];
    const int ldr = tid >> 2;        // base row for it=0 (idx>>2)
    const int ldkg = tid & 3;        // k-group (8 floats each)

#define LOAD_CHUNK(c)                                                          \
    {                                                                          \
        const int kc = (c) * 32;                                               \
        _Pragma("unroll")                                                      \
        for (int it = 0; it < 2; it++) {                                       \
            const int r = ldr + it * 64;                                       \
            const float* ap = A + (size_t)(m0 + r) * GK + kc + ldkg * 8;       \
            sA[it][0] = *(const float4*)ap;                                    \
            sA[it][1] = *(const float4*)(ap + 4);                              \
            const float* bp = B + (size_t)(n0 + r) * GK + kc + ldkg * 8;       \
            sB[it][0] = *(const float4*)bp;                                    \
            sB[it][1] = *(const float4*)(bp + 4);                              \
        }                                                                      \
    }

#define STORE_CHUNK(buf)                                                       \
    {                                                                          \
        const uint32_t ab = smb + (buf) * 32768;                               \
        _Pragma("unroll")                                                      \
        for (int it = 0; it < 2; it++) {                                       \
            const int r = ldr + it * 64;                                       \
            const uint32_t offh = (uint32_t)(r * 128 + ldkg * 16);             \
            uint32_t h0, l0, h1, l1, h2, l2, h3, l3;                           \
            split2(sA[it][0].x, sA[it][0].y, h0, l0);                          \
            split2(sA[it][0].z, sA[it][0].w, h1, l1);                          \
            split2(sA[it][1].x, sA[it][1].y, h2, l2);                          \
            split2(sA[it][1].z, sA[it][1].w, h3, l3);                          \
            *(uint4*)(sm + (buf) * 32768 + SW128(offh)) =                      \
                make_uint4(h0, h1, h2, h3);                                    \
            *(uint4*)(sm + (buf) * 32768 + SW128(offh + 64)) =                 \
                make_uint4(l0, l1, l2, l3);                                    \
            split2(sB[it][0].x, sB[it][0].y, h0, l0);                          \
            split2(sB[it][0].z, sB[it][0].w, h1, l1);                          \
            split2(sB[it][1].x, sB[it][1].y, h2, l2);                          \
            split2(sB[it][1].z, sB[it][1].w, h3, l3);                          \
            *(uint4*)(sm + (buf) * 32768 + 16384 + SW128(offh)) =              \
                make_uint4(h0, h1, h2, h3);                                    \
            *(uint4*)(sm + (buf) * 32768 + 16384 + SW128(offh + 64)) =         \
                make_uint4(l0, l1, l2, l3);                                    \
        }                                                                      \
    }

    LOAD_CHUNK(0);
    STORE_CHUNK(0);
    __syncthreads();

    for (int c = 0; c < 32; c++) {
        const int buf = c & 1;
        if (c < 31) LOAD_CHUNK(c + 1);

        // ---------------- compute on buf ----------------
        const uint32_t abase = smb + buf * 32768;
        const uint32_t bbase = abase + 16384;
#pragma unroll
        for (int kk = 0; kk < 2; kk++) {
            uint32_t ah[2][4], al[2][4];
#pragma unroll
            for (int sub = 0; sub < 2; sub++) {
                const uint32_t row = (uint32_t)(wm * 32 + sub * 16 + (lid & 15));
                const uint32_t col2 = (uint32_t)((kk * 16 + ((lid >> 4) << 3)) * 2);
                const uint32_t off = row * 128 + col2;
                ldsm_x4(ah[sub][0], ah[sub][1], ah[sub][2], ah[sub][3],
                        abase + SW128(off));
                ldsm_x4(al[sub][0], al[sub][1], al[sub][2], al[sub][3],
                        abase + SW128(off + 64));
            }
            uint32_t bh[8][2], bl[8][2];
#pragma unroll
            for (int nt = 0; nt < 4; nt++) {
                const uint32_t rown =
                    (uint32_t)(wn * 64 + nt * 16 + (lid & 7) + ((lid & 16) ? 8 : 0));
                const uint32_t colb = (uint32_t)((kk * 16 + ((lid & 8) ? 8 : 0)) * 2);
                const uint32_t off = rown * 128 + colb;
                uint32_t r0, r1, r2, r3;
                ldsm_x4(r0, r1, r2, r3, bbase + SW128(off));
                bh[nt * 2][0] = r0; bh[nt * 2][1] = r1;
                bh[nt * 2 + 1][0] = r2; bh[nt * 2 + 1][1] = r3;
                ldsm_x4(r0, r1, r2, r3, bbase + SW128(off + 64));
                bl[nt * 2][0] = r0; bl[nt * 2][1] = r1;
                bl[nt * 2 + 1][0] = r2; bl[nt * 2 + 1][1] = r3;
            }
#pragma unroll
            for (int sub = 0; sub < 2; sub++)
#pragma unroll
                for (int j = 0; j < 8; j++) {
                    mma_bf16(acc[sub][j], ah[sub], bh[j]);   // hi*hi
                    mma_bf16(acc[sub][j], ah[sub], bl[j]);   // hi*lo
                    mma_bf16(acc[sub][j], al[sub], bh[j]);   // lo*hi
                }
        }
        // ------------------------------------------------

        if (c < 31) STORE_CHUNK((c + 1) & 1);
        __syncthreads();
    }

    // Epilogue: fragment -> global
    const int tr = lid >> 2;
    const int tc = (lid & 3) * 2;
#pragma unroll
    for (int sub = 0; sub < 2; sub++) {
        const int m = m0 + wm * 32 + sub * 16 + tr;
#pragma unroll
        for (int j = 0; j < 8; j++) {
            const int n = n0 + wn * 64 + j * 8 + tc;
            *(float2*)(C + (size_t)m * ldc + n) =
                make_float2(acc[sub][j][0], acc[sub][j][1]);
            *(float2*)(C + (size_t)(m + 8) * ldc + n) =
                make_float2(acc[sub][j][2], acc[sub][j][3]);
        }
    }
#undef LOAD_CHUNK
#undef STORE_CHUNK
}

// ===========================================================================
// Weight concat: g_wcat = [WQ; WK; WV]  (1536 x 1024)
// ===========================================================================
__global__ void concat_w(const float4* __restrict__ WQ, const float4* __restrict__ WK,
                         const float4* __restrict__ WV, float4* __restrict__ W) {
    const int i = blockIdx.x * 256 + threadIdx.x;
    if (i < 262144)      W[i] = WQ[i];
    else if (i < 327680) W[i] = WK[i - 262144];
    else                 W[i] = WV[i - 327680];
}

// ===========================================================================
// RoPE (in place over Q cols 0..1023 and K cols 1024..1279)
// ===========================================================================
__global__ void rope_kernel(float* __restrict__ QKV, const int* __restrict__ tpos) {
    const int row = blockIdx.x;
    const int t = row & (TFULL - 1);
    const float pos = (float)tpos[t];
    float* rp = QKV + (size_t)row * LDQKV;
    for (int p = threadIdx.x; p < 640; p += blockDim.x) {
        const int c0 = 2 * p;
        const int pp = (c0 & 63) >> 1;
        const float inv_freq = __expf(-0.28782313662425572f * (float)pp);
        const float ang = pos * inv_freq;
        float s, c;
        sincosf(ang, &s, &c);
        const float x1 = rp[c0], x2 = rp[c0 + 1];
        rp[c0]     = x1 * c - x2 * s;
        rp[c0 + 1] = x1 * s + x2 * c;
    }
}

// ===========================================================================
// Sliding-window causal attention (scalar fp32, online softmax)
// ===========================================================================
__global__ __launch_bounds__(128)
void attn_kernel(const float* __restrict__ QKV, float* __restrict__ O) {
    __shared__ float4 Ks[32][16];
    __shared__ float4 Vs[32][16];
    const int tid = threadIdx.x;
    const int i0 = blockIdx.x * 128;
    const int h  = blockIdx.y;
    const int bb = blockIdx.z;
    const int g  = h >> 2;
    const int i  = i0 + tid;

    const float* qrow = QKV + ((size_t)(bb * TFULL + i)) * LDQKV + h * 64;
    float4 q4[16];
#pragma unroll
    for (int u = 0; u < 16; u++) {
        float4 v = *(const float4*)(qrow + 4 * u);
        v.x *= 0.125f; v.y *= 0.125f; v.z *= 0.125f; v.w *= 0.125f;
        q4[u] = v;
    }

    float m = -1e30f, l = 0.f;
    float4 acc[16];
#pragma unroll
    for (int u = 0; u < 16; u++) acc[u] = make_float4(0.f, 0.f, 0.f, 0.f);

    const int j0   = (i0 - 512 > 0) ? (i0 - 512) : 0;
    const int jend = i0 + 127;

    for (int jc = j0; jc <= jend; jc += 32) {
        __syncthreads();
        for (int idx = tid; idx < 512; idx += 128) {
            const int rr = idx >> 4, cc = idx & 15;
            const size_t base = ((size_t)(bb * TFULL + jc + rr)) * LDQKV + g * 64 + 4 * cc;
            Ks[rr][cc] = *(const float4*)(QKV + base + 1024);
            Vs[rr][cc] = *(const float4*)(QKV + base + 1280);
        }
        __syncthreads();

        int rlo = (i - 512) - jc; if (rlo < 0) rlo = 0;
        int rmax = i - jc;        if (rmax > 31) rmax = 31;

        for (int rr = rlo; rr <= rmax; rr++) {
            float s = 0.f;
#pragma unroll
            for (int u = 0; u < 16; u++) {
                float4 k4 = Ks[rr][u];
                s += q4[u].x * k4.x + q4[u].y * k4.y + q4[u].z * k4.z + q4[u].w * k4.w;
            }
            if (s > m) {
                const float corr = __expf(m - s);
                l *= corr;
#pragma unroll
                for (int u = 0; u < 16; u++) {
                    acc[u].x *= corr; acc[u].y *= corr;
                    acc[u].z *= corr; acc[u].w *= corr;
                }
                m = s;
            }
            const float p = __expf(s - m);
            l += p;
#pragma unroll
            for (int u = 0; u < 16; u++) {
                float4 v4 = Vs[rr][u];
                acc[u].x += p * v4.x; acc[u].y += p * v4.y;
                acc[u].z += p * v4.z; acc[u].w += p * v4.w;
            }
        }
    }

    const float inv = 1.f / l;
    float* orow = O + ((size_t)(bb * TFULL + i)) * DM + h * 64;
#pragma unroll
    for (int u = 0; u < 16; u++) {
        float4 v = acc[u];
        v.x *= inv; v.y *= inv; v.z *= inv; v.w *= inv;
        *(float4*)(orow + 4 * u) = v;
    }
}

// ===========================================================================
extern "C" void kernel_launch(void* const* d_in, const int* in_sizes, int n_in,
                              void* d_out, int out_size) {
    const float* x  = (const float*)d_in[0];
    const float* WQ = (const float*)d_in[1];
    const float* WK = (const float*)d_in[2];
    const float* WV = (const float*)d_in[3];
    const float* WO = (const float*)d_in[4];
    const int* tpos = (const int*)d_in[5];

    float *qkv, *att, *wcat;
    cudaGetSymbolAddress((void**)&qkv, g_qkv);
    cudaGetSymbolAddress((void**)&att, g_att);
    cudaGetSymbolAddress((void**)&wcat, g_wcat);

    cudaFuncSetAttribute(gemm_bf16x3, cudaFuncAttributeMaxDynamicSharedMemorySize,
                         SM_GEMM);

    concat_w<<<1536, 256>>>((const float4*)WQ, (const float4*)WK, (const float4*)WV,
                            (float4*)wcat);

    // QKV projection: [4096,1536] = x @ Wcat^T, ldc=1536
    gemm_bf16x3<<<dim3(12, 32), 256, SM_GEMM>>>(x, wcat, qkv, LDQKV);

    rope_kernel<<<2 * TFULL, 128>>>(qkv, tpos);

    attn_kernel<<<dim3(TFULL / 128, 16, 2), 128>>>(qkv, att);

    // Output projection straight into d_out
    gemm_bf16x3<<<dim3(8, 32), 256, SM_GEMM>>>(att, WO, (float*)d_out, DM);
}

// round 4
// speedup vs baseline: 4.0417x; 2.4299x over previous
#include <cuda_runtime.h>
#include <cuda_bf16.h>
#include <cuda_fp16.h>
#include <math.h>
#include <stdint.h>

#define TFULL 2048
#define DM    1024
#define LDQKV 1536   // [Q(1024) | K(256) | V(256)]

// Scratch (static device globals — no allocation allowed)
__device__ float  g_qkv[2 * TFULL * LDQKV];      // 25.2 MB fp32 projections
__device__ float  g_att[2 * TFULL * DM];         // 16.8 MB attention out
__device__ float  g_wcat[1536 * 1024];           // 6.3 MB concat WQ|WK|WV
__device__ __half g_q16[2 * 16 * TFULL * 64];    // 8.4 MB  [b][h][t][64]
__device__ __half g_k16[2 * 4 * TFULL * 64];     // 2.1 MB  [b][g][t][64]
__device__ __half g_v16t[2 * 4 * 64 * TFULL];    // 2.1 MB  [b][g][dim][t]

// ===========================================================================
// Helpers
// ===========================================================================
__device__ __forceinline__ uint32_t smem_u32(const void* p) {
    uint32_t a;
    asm("{ .reg .u64 t; cvta.to.shared.u64 t, %1; cvt.u32.u64 %0, t; }"
        : "=r"(a) : "l"(p));
    return a;
}
__device__ __forceinline__ void ldsm_x4(uint32_t& r0, uint32_t& r1, uint32_t& r2,
                                        uint32_t& r3, uint32_t addr) {
    asm volatile("ldmatrix.sync.aligned.m8n8.x4.shared.b16 {%0,%1,%2,%3}, [%4];"
                 : "=r"(r0), "=r"(r1), "=r"(r2), "=r"(r3) : "r"(addr));
}
__device__ __forceinline__ void mma_bf16(float* c, const uint32_t* a, const uint32_t* b) {
    asm volatile(
        "mma.sync.aligned.m16n8k16.row.col.f32.bf16.bf16.f32 "
        "{%0,%1,%2,%3}, {%4,%5,%6,%7}, {%8,%9}, {%0,%1,%2,%3};"
        : "+f"(c[0]), "+f"(c[1]), "+f"(c[2]), "+f"(c[3])
        : "r"(a[0]), "r"(a[1]), "r"(a[2]), "r"(a[3]), "r"(b[0]), "r"(b[1]));
}
__device__ __forceinline__ void mma_f16(float* c, const uint32_t* a, const uint32_t* b) {
    asm volatile(
        "mma.sync.aligned.m16n8k16.row.col.f32.f16.f16.f32 "
        "{%0,%1,%2,%3}, {%4,%5,%6,%7}, {%8,%9}, {%0,%1,%2,%3};"
        : "+f"(c[0]), "+f"(c[1]), "+f"(c[2]), "+f"(c[3])
        : "r"(a[0]), "r"(a[1]), "r"(a[2]), "r"(a[3]), "r"(b[0]), "r"(b[1]));
}
// pack two floats: a -> lower half, b -> upper half
__device__ __forceinline__ uint32_t pack_bf16(float a, float b) {
    uint32_t r;
    asm("cvt.rn.bf16x2.f32 %0, %1, %2;" : "=r"(r) : "f"(b), "f"(a));
    return r;
}
__device__ __forceinline__ uint32_t pack_f16(float a, float b) {
    uint32_t r;
    asm("cvt.rn.f16x2.f32 %0, %1, %2;" : "=r"(r) : "f"(b), "f"(a));
    return r;
}
// split pair: hi = bf16(x), lo = bf16(x - hi)
__device__ __forceinline__ void split2(float x0, float x1, uint32_t& hi, uint32_t& lo) {
    hi = pack_bf16(x0, x1);
    float h0 = __bfloat162float(__ushort_as_bfloat16((unsigned short)(hi & 0xFFFF)));
    float h1 = __bfloat162float(__ushort_as_bfloat16((unsigned short)(hi >> 16)));
    lo = pack_bf16(x0 - h0, x1 - h1);
}
#define SW128(off) ((off) ^ (((off) >> 3) & 0x70))

// ===========================================================================
// 3xBF16 split GEMM via mma.sync (unchanged from R3 — verified correct)
// ===========================================================================
#define GK 1024
#define SM_GEMM 65536

__global__ __launch_bounds__(256, 1)
void gemm_bf16x3(const float* __restrict__ A, const float* __restrict__ B,
                 float* __restrict__ C, int ldc) {
    extern __shared__ char sm[];
    const uint32_t smb = smem_u32(sm);
    const int tid = threadIdx.x;
    const int lid = tid & 31;
    const int wid = tid >> 5;
    const int wm = wid & 3;
    const int wn = wid >> 2;
    const int m0 = blockIdx.y * 128;
    const int n0 = blockIdx.x * 128;

    float acc[2][8][4];
#pragma unroll
    for (int s = 0; s < 2; s++)
#pragma unroll
        for (int j = 0; j < 8; j++)
#pragma unroll
            for (int q = 0; q < 4; q++) acc[s][j][q] = 0.f;

    float4 sA[2][2], sB[2][2];
    const int ldr = tid >> 2;
    const int ldkg = tid & 3;

#define LOAD_CHUNK(c)                                                          \
    {                                                                          \
        const int kc = (c) * 32;                                               \
        _Pragma("unroll")                                                      \
        for (int it = 0; it < 2; it++) {                                       \
            const int r = ldr + it * 64;                                       \
            const float* ap = A + (size_t)(m0 + r) * GK + kc + ldkg * 8;       \
            sA[it][0] = *(const float4*)ap;                                    \
            sA[it][1] = *(const float4*)(ap + 4);                              \
            const float* bp = B + (size_t)(n0 + r) * GK + kc + ldkg * 8;       \
            sB[it][0] = *(const float4*)bp;                                    \
            sB[it][1] = *(const float4*)(bp + 4);                              \
        }                                                                      \
    }

#define STORE_CHUNK(buf)                                                       \
    {                                                                          \
        _Pragma("unroll")                                                      \
        for (int it = 0; it < 2; it++) {                                       \
            const int r = ldr + it * 64;                                       \
            const uint32_t offh = (uint32_t)(r * 128 + ldkg * 16);             \
            uint32_t h0, l0, h1, l1, h2, l2, h3, l3;                           \
            split2(sA[it][0].x, sA[it][0].y, h0, l0);                          \
            split2(sA[it][0].z, sA[it][0].w, h1, l1);                          \
            split2(sA[it][1].x, sA[it][1].y, h2, l2);                          \
            split2(sA[it][1].z, sA[it][1].w, h3, l3);                          \
            *(uint4*)(sm + (buf) * 32768 + SW128(offh)) =                      \
                make_uint4(h0, h1, h2, h3);                                    \
            *(uint4*)(sm + (buf) * 32768 + SW128(offh + 64)) =                 \
                make_uint4(l0, l1, l2, l3);                                    \
            split2(sB[it][0].x, sB[it][0].y, h0, l0);                          \
            split2(sB[it][0].z, sB[it][0].w, h1, l1);                          \
            split2(sB[it][1].x, sB[it][1].y, h2, l2);                          \
            split2(sB[it][1].z, sB[it][1].w, h3, l3);                          \
            *(uint4*)(sm + (buf) * 32768 + 16384 + SW128(offh)) =              \
                make_uint4(h0, h1, h2, h3);                                    \
            *(uint4*)(sm + (buf) * 32768 + 16384 + SW128(offh + 64)) =         \
                make_uint4(l0, l1, l2, l3);                                    \
        }                                                                      \
    }

    LOAD_CHUNK(0);
    STORE_CHUNK(0);
    __syncthreads();

    for (int c = 0; c < 32; c++) {
        const int buf = c & 1;
        if (c < 31) LOAD_CHUNK(c + 1);

        const uint32_t abase = smb + buf * 32768;
        const uint32_t bbase = abase + 16384;
#pragma unroll
        for (int kk = 0; kk < 2; kk++) {
            uint32_t ah[2][4], al[2][4];
#pragma unroll
            for (int sub = 0; sub < 2; sub++) {
                const uint32_t row = (uint32_t)(wm * 32 + sub * 16 + (lid & 15));
                const uint32_t col2 = (uint32_t)((kk * 16 + ((lid >> 4) << 3)) * 2);
                const uint32_t off = row * 128 + col2;
                ldsm_x4(ah[sub][0], ah[sub][1], ah[sub][2], ah[sub][3],
                        abase + SW128(off));
                ldsm_x4(al[sub][0], al[sub][1], al[sub][2], al[sub][3],
                        abase + SW128(off + 64));
            }
            uint32_t bh[8][2], bl[8][2];
#pragma unroll
            for (int nt = 0; nt < 4; nt++) {
                const uint32_t rown =
                    (uint32_t)(wn * 64 + nt * 16 + (lid & 7) + ((lid & 16) ? 8 : 0));
                const uint32_t colb = (uint32_t)((kk * 16 + ((lid & 8) ? 8 : 0)) * 2);
                const uint32_t off = rown * 128 + colb;
                uint32_t r0, r1, r2, r3;
                ldsm_x4(r0, r1, r2, r3, bbase + SW128(off));
                bh[nt * 2][0] = r0; bh[nt * 2][1] = r1;
                bh[nt * 2 + 1][0] = r2; bh[nt * 2 + 1][1] = r3;
                ldsm_x4(r0, r1, r2, r3, bbase + SW128(off + 64));
                bl[nt * 2][0] = r0; bl[nt * 2][1] = r1;
                bl[nt * 2 + 1][0] = r2; bl[nt * 2 + 1][1] = r3;
            }
#pragma unroll
            for (int sub = 0; sub < 2; sub++)
#pragma unroll
                for (int j = 0; j < 8; j++) {
                    mma_bf16(acc[sub][j], ah[sub], bh[j]);
                    mma_bf16(acc[sub][j], ah[sub], bl[j]);
                    mma_bf16(acc[sub][j], al[sub], bh[j]);
                }
        }

        if (c < 31) STORE_CHUNK((c + 1) & 1);
        __syncthreads();
    }

    const int tr = lid >> 2;
    const int tc = (lid & 3) * 2;
#pragma unroll
    for (int sub = 0; sub < 2; sub++) {
        const int m = m0 + wm * 32 + sub * 16 + tr;
#pragma unroll
        for (int j = 0; j < 8; j++) {
            const int n = n0 + wn * 64 + j * 8 + tc;
            *(float2*)(C + (size_t)m * ldc + n) =
                make_float2(acc[sub][j][0], acc[sub][j][1]);
            *(float2*)(C + (size_t)(m + 8) * ldc + n) =
                make_float2(acc[sub][j][2], acc[sub][j][3]);
        }
    }
#undef LOAD_CHUNK
#undef STORE_CHUNK
}

// ===========================================================================
// Weight concat
// ===========================================================================
__global__ void concat_w(const float4* __restrict__ WQ, const float4* __restrict__ WK,
                         const float4* __restrict__ WV, float4* __restrict__ W) {
    const int i = blockIdx.x * 256 + threadIdx.x;
    if (i < 262144)      W[i] = WQ[i];
    else if (i < 327680) W[i] = WK[i - 262144];
    else                 W[i] = WV[i - 327680];
}

// ===========================================================================
// RoPE + fp16 emit: Q (scaled by log2e/8) -> g_q16 [b][h][t][64],
// K -> g_k16 [b][g][t][64], V -> g_v16t [b][g][dim][t]
// ===========================================================================
#define QSCALE 0.18033688011112043f   // log2(e) / 8

__global__ void rope_fp16(const float* __restrict__ QKV, const int* __restrict__ tpos,
                          __half* __restrict__ Q16, __half* __restrict__ K16,
                          __half* __restrict__ V16t) {
    const int row = blockIdx.x;               // 0..4095
    const int bb = row >> 11;
    const int t = row & (TFULL - 1);
    const float pos = (float)tpos[t];
    const float* rp = QKV + (size_t)row * LDQKV;
    const int tid = threadIdx.x;

    // Q: 512 rotation pairs
    for (int p = tid; p < 512; p += 128) {
        const int head = p >> 5, pp = p & 31;
        const int c0 = head * 64 + 2 * pp;
        const float inv_freq = __expf(-0.28782313662425572f * (float)pp);
        const float ang = pos * inv_freq;
        float s, c;
        sincosf(ang, &s, &c);
        const float x1 = rp[c0], x2 = rp[c0 + 1];
        const float r1 = (x1 * c - x2 * s) * QSCALE;
        const float r2 = (x1 * s + x2 * c) * QSCALE;
        *(__half2*)(Q16 + ((size_t)((bb * 16 + head) * TFULL + t)) * 64 + 2 * pp) =
            __floats2half2_rn(r1, r2);
    }
    // K: 128 rotation pairs
    if (tid < 128) {
        const int g = tid >> 5, pp = tid & 31;
        const int c0 = 1024 + g * 64 + 2 * pp;
        const float inv_freq = __expf(-0.28782313662425572f * (float)pp);
        const float ang = pos * inv_freq;
        float s, c;
        sincosf(ang, &s, &c);
        const float x1 = rp[c0], x2 = rp[c0 + 1];
        *(__half2*)(K16 + ((size_t)((bb * 4 + g) * TFULL + t)) * 64 + 2 * pp) =
            __floats2half2_rn(x1 * c - x2 * s, x1 * s + x2 * c);
    }
    // V: 256 elements, transposed store
    for (int e = tid; e < 256; e += 128) {
        const int g = e >> 6, d = e & 63;
        V16t[((size_t)((bb * 4 + g) * 64 + d)) * TFULL + t] =
            __float2half(rp[1280 + e]);
    }
}

// ===========================================================================
// fp16 mma flash attention. Grid (t/64, heads, b), 128 threads (4 warps).
// Warp w owns query rows [i0+16w, i0+16w+16). Keys chunked 64-wide.
// ===========================================================================
__global__ __launch_bounds__(128)
void attn_mma(const __half* __restrict__ Q16, const __half* __restrict__ K16,
              const __half* __restrict__ V16t, float* __restrict__ O) {
    __shared__ __align__(1024) char smQ[8192];
    __shared__ __align__(1024) char smK[8192];
    __shared__ __align__(1024) char smV[8192];
    const int tid = threadIdx.x, lid = tid & 31, w = tid >> 5;
    const int i0 = blockIdx.x * 64;
    const int h = blockIdx.y, bb = blockIdx.z, g = h >> 2;

    // Load Q tile (64x64 fp16), SW128-swizzled
    const __half* qg = Q16 + ((size_t)((bb * 16 + h) * TFULL + i0)) * 64;
#pragma unroll
    for (int u = 0; u < 4; u++) {
        const int idx = tid + 128 * u;
        const int r = idx >> 3, c = idx & 7;
        *(uint4*)(smQ + SW128((uint32_t)(r * 128 + c * 16))) =
            *(const uint4*)(qg + (size_t)r * 64 + c * 8);
    }
    __syncthreads();

    // Q A-fragments (constant across chunks)
    const uint32_t smbQ = smem_u32(smQ);
    uint32_t qa[4][4];
#pragma unroll
    for (int ks = 0; ks < 4; ks++) {
        const uint32_t off =
            (uint32_t)((w * 16 + (lid & 15)) * 128 + (ks * 16 + ((lid >> 4) << 3)) * 2);
        ldsm_x4(qa[ks][0], qa[ks][1], qa[ks][2], qa[ks][3], smbQ + SW128(off));
    }

    float oacc[8][4];
#pragma unroll
    for (int j = 0; j < 8; j++)
#pragma unroll
        for (int q = 0; q < 4; q++) oacc[j][q] = 0.f;
    float m0 = -1e30f, m1 = -1e30f, l0 = 0.f, l1 = 0.f;

    const int j0 = (i0 - 512 > 0) ? (i0 - 512) : 0;
    const uint32_t smbK = smem_u32(smK), smbV = smem_u32(smV);
    const __half* kgb = K16 + ((size_t)((bb * 4 + g) * TFULL)) * 64;
    const __half* vgb = V16t + ((size_t)((bb * 4 + g) * 64)) * TFULL;

    for (int jc = j0; jc <= i0; jc += 64) {
        __syncthreads();
#pragma unroll
        for (int u = 0; u < 4; u++) {
            const int idx = tid + 128 * u;
            const int r = idx >> 3, c = idx & 7;
            const uint32_t d = SW128((uint32_t)(r * 128 + c * 16));
            *(uint4*)(smK + d) = *(const uint4*)(kgb + (size_t)(jc + r) * 64 + c * 8);
            *(uint4*)(smV + d) = *(const uint4*)(vgb + (size_t)r * TFULL + jc + c * 8);
        }
        __syncthreads();

        // S = Q @ K^T  (warp: 16 queries x 64 keys)
        float sacc[8][4];
#pragma unroll
        for (int j = 0; j < 8; j++)
#pragma unroll
            for (int q = 0; q < 4; q++) sacc[j][q] = 0.f;
#pragma unroll
        for (int ks = 0; ks < 4; ks++) {
            uint32_t kb[8][2];
#pragma unroll
            for (int nt = 0; nt < 4; nt++) {
                const uint32_t off =
                    (uint32_t)((nt * 16 + (lid & 7) + ((lid & 16) ? 8 : 0)) * 128 +
                               (ks * 16 + ((lid & 8) ? 8 : 0)) * 2);
                uint32_t r0, r1, r2, r3;
                ldsm_x4(r0, r1, r2, r3, smbK + SW128(off));
                kb[nt * 2][0] = r0; kb[nt * 2][1] = r1;
                kb[nt * 2 + 1][0] = r2; kb[nt * 2 + 1][1] = r3;
            }
#pragma unroll
            for (int j = 0; j < 8; j++) mma_f16(sacc[j], qa[ks], kb[j]);
        }

        // Mask (only first chunk at full window, and diagonal chunk)
        if (jc == i0 || i0 - jc == 512) {
            const int r0 = i0 + w * 16 + (lid >> 2), r1 = r0 + 8;
#pragma unroll
            for (int j = 0; j < 8; j++) {
                const int c0 = jc + j * 8 + 2 * (lid & 3);
                if (c0 > r0 || r0 - c0 > 512)         sacc[j][0] = -1e30f;
                if (c0 + 1 > r0 || r0 - c0 - 1 > 512) sacc[j][1] = -1e30f;
                if (c0 > r1 || r1 - c0 > 512)         sacc[j][2] = -1e30f;
                if (c0 + 1 > r1 || r1 - c0 - 1 > 512) sacc[j][3] = -1e30f;
            }
        }

        // Online softmax (rows r0 = tr, r1 = tr+8 per thread; quad holds a row)
        float mx0 = -1e30f, mx1 = -1e30f;
#pragma unroll
        for (int j = 0; j < 8; j++) {
            mx0 = fmaxf(mx0, fmaxf(sacc[j][0], sacc[j][1]));
            mx1 = fmaxf(mx1, fmaxf(sacc[j][2], sacc[j][3]));
        }
        mx0 = fmaxf(mx0, __shfl_xor_sync(0xffffffff, mx0, 1));
        mx0 = fmaxf(mx0, __shfl_xor_sync(0xffffffff, mx0, 2));
        mx1 = fmaxf(mx1, __shfl_xor_sync(0xffffffff, mx1, 1));
        mx1 = fmaxf(mx1, __shfl_xor_sync(0xffffffff, mx1, 2));
        const float mn0 = fmaxf(m0, mx0), mn1 = fmaxf(m1, mx1);
        const float corr0 = exp2f(m0 - mn0), corr1 = exp2f(m1 - mn1);
        float sum0 = 0.f, sum1 = 0.f;
#pragma unroll
        for (int j = 0; j < 8; j++) {
            sacc[j][0] = exp2f(sacc[j][0] - mn0);
            sacc[j][1] = exp2f(sacc[j][1] - mn0);
            sacc[j][2] = exp2f(sacc[j][2] - mn1);
            sacc[j][3] = exp2f(sacc[j][3] - mn1);
            sum0 += sacc[j][0] + sacc[j][1];
            sum1 += sacc[j][2] + sacc[j][3];
        }
        sum0 += __shfl_xor_sync(0xffffffff, sum0, 1);
        sum0 += __shfl_xor_sync(0xffffffff, sum0, 2);
        sum1 += __shfl_xor_sync(0xffffffff, sum1, 1);
        sum1 += __shfl_xor_sync(0xffffffff, sum1, 2);
        l0 = l0 * corr0 + sum0;
        l1 = l1 * corr1 + sum1;
        m0 = mn0; m1 = mn1;
#pragma unroll
        for (int j = 0; j < 8; j++) {
            oacc[j][0] *= corr0; oacc[j][1] *= corr0;
            oacc[j][2] *= corr1; oacc[j][3] *= corr1;
        }

        // Pack P to fp16 A-fragments (accumulator layout == A layout)
        uint32_t pa[4][4];
#pragma unroll
        for (int k = 0; k < 4; k++) {
            pa[k][0] = pack_f16(sacc[2 * k][0], sacc[2 * k][1]);
            pa[k][1] = pack_f16(sacc[2 * k][2], sacc[2 * k][3]);
            pa[k][2] = pack_f16(sacc[2 * k + 1][0], sacc[2 * k + 1][1]);
            pa[k][3] = pack_f16(sacc[2 * k + 1][2], sacc[2 * k + 1][3]);
        }

        // O += P @ V  (V stored [dim][key] -> non-trans ldmatrix = B frags)
#pragma unroll
        for (int ks = 0; ks < 4; ks++) {
            uint32_t vb[8][2];
#pragma unroll
            for (int nt = 0; nt < 4; nt++) {
                const uint32_t off =
                    (uint32_t)((nt * 16 + (lid & 7) + ((lid & 16) ? 8 : 0)) * 128 +
                               (ks * 16 + ((lid & 8) ? 8 : 0)) * 2);
                uint32_t r0, r1, r2, r3;
                ldsm_x4(r0, r1, r2, r3, smbV + SW128(off));
                vb[nt * 2][0] = r0; vb[nt * 2][1] = r1;
                vb[nt * 2 + 1][0] = r2; vb[nt * 2 + 1][1] = r3;
            }
#pragma unroll
            for (int j = 0; j < 8; j++) mma_f16(oacc[j], pa[ks], vb[j]);
        }
    }

    // Epilogue
    const float inv0 = 1.f / l0, inv1 = 1.f / l1;
    const int qr0 = i0 + w * 16 + (lid >> 2);
    float* ob = O + ((size_t)(bb * TFULL)) * DM + h * 64;
#pragma unroll
    for (int j = 0; j < 8; j++) {
        const int col = j * 8 + 2 * (lid & 3);
        *(float2*)(ob + (size_t)qr0 * DM + col) =
            make_float2(oacc[j][0] * inv0, oacc[j][1] * inv0);
        *(float2*)(ob + (size_t)(qr0 + 8) * DM + col) =
            make_float2(oacc[j][2] * inv1, oacc[j][3] * inv1);
    }
}

// ===========================================================================
extern "C" void kernel_launch(void* const* d_in, const int* in_sizes, int n_in,
                              void* d_out, int out_size) {
    const float* x  = (const float*)d_in[0];
    const float* WQ = (const float*)d_in[1];
    const float* WK = (const float*)d_in[2];
    const float* WV = (const float*)d_in[3];
    const float* WO = (const float*)d_in[4];
    const int* tpos = (const int*)d_in[5];

    float *qkv, *att, *wcat;
    __half *q16, *k16, *v16t;
    cudaGetSymbolAddress((void**)&qkv, g_qkv);
    cudaGetSymbolAddress((void**)&att, g_att);
    cudaGetSymbolAddress((void**)&wcat, g_wcat);
    cudaGetSymbolAddress((void**)&q16, g_q16);
    cudaGetSymbolAddress((void**)&k16, g_k16);
    cudaGetSymbolAddress((void**)&v16t, g_v16t);

    cudaFuncSetAttribute(gemm_bf16x3, cudaFuncAttributeMaxDynamicSharedMemorySize,
                         SM_GEMM);

    concat_w<<<1536, 256>>>((const float4*)WQ, (const float4*)WK, (const float4*)WV,
                            (float4*)wcat);

    // QKV projection: [4096,1536] = x @ Wcat^T, ldc=1536
    gemm_bf16x3<<<dim3(12, 32), 256, SM_GEMM>>>(x, wcat, qkv, LDQKV);

    // RoPE + fp16 staging
    rope_fp16<<<2 * TFULL, 128>>>(qkv, tpos, q16, k16, v16t);

    // Flash attention (fp16 mma)
    attn_mma<<<dim3(TFULL / 64, 16, 2), 128>>>(q16, k16, v16t, att);

    // Output projection straight into d_out
    gemm_bf16x3<<<dim3(8, 32), 256, SM_GEMM>>>(att, WO, (float*)d_out, DM);
}